// round 2
// baseline (speedup 1.0000x reference)
#include <cuda_runtime.h>
#include <cstdint>

// Segment offsets scratch: offsets[n] = first edge index whose segment id >= n.
// N = out_size / D = 100000 for this problem; capacity with headroom.
#define MAX_SEGMENTS 131072
__device__ int g_offsets[MAX_SEGMENTS + 1];
__device__ int g_idx_is64;   // 1 if index buffer is int64, 0 if int32

// ---------------------------------------------------------------------------
// Kernel 0: dtype detection. JAX with x64 disabled silently downcasts the
// reference's int64 index to int32; we must handle both. For an int64 buffer
// with values < 2^31, every odd-indexed 32-bit word is a zero high-half.
// For an int32 sorted index, words near the end are ~N-1 != 0. Only reads
// words < E, valid for both layouts.
// ---------------------------------------------------------------------------
__global__ void detect_idx_dtype_kernel(const unsigned int* __restrict__ w, int E) {
    int j = E - 1;
    if ((j & 1) == 0) j -= 1;           // largest odd word index < E
    unsigned int acc = 0;
    for (int k = 0; k < 3 && j - 2 * k >= 1; ++k)
        acc |= w[j - 2 * k];
    g_idx_is64 = (acc == 0) ? 1 : 0;
}

// ---------------------------------------------------------------------------
// Kernel 1: offsets[n] = lower_bound(index, n) over the sorted index.
// One thread per segment boundary (n in [0, N]). ~20 iterations, mostly L2 hits.
// ---------------------------------------------------------------------------
__global__ void build_offsets_kernel(const void* __restrict__ index_raw,
                                     int E, int N) {
    int n = blockIdx.x * blockDim.x + threadIdx.x;
    if (n > N) return;
    int lo = 0, hi = E;
    if (g_idx_is64) {
        const long long* index = (const long long*)index_raw;
        long long target = (long long)n;
        while (lo < hi) {
            int mid = (lo + hi) >> 1;
            if (index[mid] < target) lo = mid + 1;
            else                     hi = mid;
        }
    } else {
        const int* index = (const int*)index_raw;
        int target = n;
        while (lo < hi) {
            int mid = (lo + hi) >> 1;
            if (index[mid] < target) lo = mid + 1;
            else                     hi = mid;
        }
    }
    g_offsets[n] = lo;
}

// ---------------------------------------------------------------------------
// Kernel 2: one warp per segment. Lane l accumulates columns [4l, 4l+4) as
// float4 over the segment's contiguous row range, then writes mean (or zeros
// for empty segments — output is poisoned, so empty rows must be written).
// Warp reads 512B contiguous per row -> fully coalesced.
// ---------------------------------------------------------------------------
__global__ void segment_mean_kernel(const float* __restrict__ x,
                                    float* __restrict__ out,
                                    int D, int N) {
    int gwarp = (blockIdx.x * blockDim.x + threadIdx.x) >> 5;
    int lane  = threadIdx.x & 31;
    if (gwarp >= N) return;

    int s = g_offsets[gwarp];
    int e = g_offsets[gwarp + 1];
    float inv = (e > s) ? (1.0f / (float)(e - s)) : 0.0f;

    // D is a multiple of 4 here (D=128 -> exactly one iteration per lane).
    for (int c = lane * 4; c < D; c += 32 * 4) {
        float4 acc = make_float4(0.f, 0.f, 0.f, 0.f);
        const float* p = x + (size_t)s * D + c;
        for (int r = s; r < e; ++r, p += D) {
            float4 v = *reinterpret_cast<const float4*>(p);
            acc.x += v.x; acc.y += v.y; acc.z += v.z; acc.w += v.w;
        }
        acc.x *= inv; acc.y *= inv; acc.z *= inv; acc.w *= inv;
        *reinterpret_cast<float4*>(out + (size_t)gwarp * D + c) = acc;
    }
}

// ---------------------------------------------------------------------------
// Launch
// Inputs (metadata order): d_in[0] = x (float32, E*D), d_in[1] = index (E,
// int32 or int64 — detected on device), d_in[2] = dim_size (unused).
// ---------------------------------------------------------------------------
extern "C" void kernel_launch(void* const* d_in, const int* in_sizes, int n_in,
                              void* d_out, int out_size) {
    const float* x   = (const float*)d_in[0];
    const void*  idx = d_in[1];
    float*       out = (float*)d_out;

    int E = in_sizes[1];          // 640000
    int D = in_sizes[0] / E;      // 128
    int N = out_size / D;         // 100000

    // Kernel 0: detect index dtype (int32 vs int64).
    detect_idx_dtype_kernel<<<1, 1>>>((const unsigned int*)idx, E);

    // Kernel 1: segment boundaries via binary search (N+1 threads).
    {
        int threads = 256;
        int blocks = (N + 1 + threads - 1) / threads;
        build_offsets_kernel<<<blocks, threads>>>(idx, E, N);
    }

    // Kernel 2: one warp per segment, 8 warps per 256-thread block.
    {
        int threads = 256;
        int warps_per_block = threads / 32;
        int blocks = (N + warps_per_block - 1) / warps_per_block;
        segment_mean_kernel<<<blocks, threads>>>(x, out, D, N);
    }
}

// round 3
// speedup vs baseline: 1.1814x; 1.1814x over previous
#include <cuda_runtime.h>
#include <cstdint>

// Segment offsets scratch: offsets[n] = first edge index whose segment id >= n.
// N = out_size / D = 100000 for this problem; capacity with headroom.
#define MAX_SEGMENTS 131072
__device__ int g_offsets[MAX_SEGMENTS + 1];

// ---------------------------------------------------------------------------
// Kernel 1: offsets[n] = lower_bound(index, n) over the sorted index.
// Dtype detection is inlined: JAX x64-disabled silently downcasts int64->int32.
// All index values < 2^31, so for int64 buffers the low 32-bit word at 2m
// carries the value; for int32 it's at m. Detection reads 3 trailing
// odd-indexed words (zero iff int64 high halves) — L1-broadcast, ~free.
// Search uses a galloping probe from the uniform-prior guess n*E/N
// (binomial std <= ~400), cutting dependent L2-latency probes ~20 -> ~12.
// ---------------------------------------------------------------------------
__global__ void build_offsets_kernel(const unsigned int* __restrict__ w,
                                     int E, int N) {
    int n = blockIdx.x * blockDim.x + threadIdx.x;
    if (n > N) return;

    // Detect int64 vs int32 (E words examined are valid under both layouts).
    int j = E - 1;
    if ((j & 1) == 0) j -= 1;
    unsigned int acc = 0;
    for (int k = 0; k < 3 && j - 2 * k >= 1; ++k)
        acc |= __ldg(&w[j - 2 * k]);
    const int shift = (acc == 0) ? 1 : 0;   // word index = m << shift

    // val(m) = low 32 bits of index[m]
    #define VALM(m) ((int)__ldg(&w[((unsigned)(m)) << shift]))

    int lo = 0, hi = E;
    // Galloping bracket around the expected position.
    int g = (int)(((long long)n * (long long)E) / (long long)N);
    if (g > E - 1) g = E - 1;
    if (g < 0) g = 0;

    if (VALM(g) < n) {
        // answer in (g, E]
        lo = g + 1;
        int step = 128;
        while (lo < E && VALM(lo) < n) {
            lo = lo + 1 + step;   // we know [old lo] < n
            step <<= 1;
        }
        // careful: re-derive valid bracket: last known "< n" is just before
        // current lo only if lo stepped; reconstruct conservatively:
        hi = (lo < E) ? lo : E;
        lo = lo - 1 - (step >> 1);      // previous probe position + 1
        if (lo < 0) lo = 0;
        if (lo > hi) lo = (g + 1 <= hi) ? g + 1 : hi;
    } else {
        // answer in [0, g]
        hi = g;
        int step = 128;
        int l = g - step;
        while (l >= 0 && VALM(l) >= n) {
            hi = l;
            step <<= 1;
            l = g - step;
        }
        lo = (l < 0) ? 0 : l + 1;
        // we only know VALM(l) < n at position l, but bracket [lo, hi) may be
        // wide; binary search below handles it.
        if (l >= 0) lo = l + 1;
        else        lo = 0;
    }

    // Binary search within bracket [lo, hi).
    while (lo < hi) {
        int mid = (lo + hi) >> 1;
        if (VALM(mid) < n) lo = mid + 1;
        else               hi = mid;
    }
    g_offsets[n] = lo;
    #undef VALM
}

// ---------------------------------------------------------------------------
// Kernel 2: one warp per segment. Lane l owns float4 column 4l (D=128 ->
// exactly one column per lane). Rows unrolled x2 with dual accumulators for
// MLP; __ldcs evict-first loads keep the read-once x stream from thrashing
// L2 (index/offsets stay resident). Empty segments write zeros (output is
// poisoned 0xAA, must be overwritten).
// ---------------------------------------------------------------------------
__global__ void segment_mean_kernel(const float* __restrict__ x,
                                    float* __restrict__ out,
                                    int D, int N) {
    int gwarp = (blockIdx.x * blockDim.x + threadIdx.x) >> 5;
    int lane  = threadIdx.x & 31;
    if (gwarp >= N) return;

    int s = g_offsets[gwarp];
    int e = g_offsets[gwarp + 1];
    int cnt = e - s;
    float inv = (cnt > 0) ? (1.0f / (float)cnt) : 0.0f;

    for (int c = lane * 4; c < D; c += 32 * 4) {
        float4 a0 = make_float4(0.f, 0.f, 0.f, 0.f);
        float4 a1 = make_float4(0.f, 0.f, 0.f, 0.f);
        const float* p = x + (size_t)s * D + c;
        int r = s;
        for (; r + 2 <= e; r += 2, p += 2 * D) {
            float4 v0 = __ldcs(reinterpret_cast<const float4*>(p));
            float4 v1 = __ldcs(reinterpret_cast<const float4*>(p + D));
            a0.x += v0.x; a0.y += v0.y; a0.z += v0.z; a0.w += v0.w;
            a1.x += v1.x; a1.y += v1.y; a1.z += v1.z; a1.w += v1.w;
        }
        if (r < e) {
            float4 v0 = __ldcs(reinterpret_cast<const float4*>(p));
            a0.x += v0.x; a0.y += v0.y; a0.z += v0.z; a0.w += v0.w;
        }
        a0.x = (a0.x + a1.x) * inv;
        a0.y = (a0.y + a1.y) * inv;
        a0.z = (a0.z + a1.z) * inv;
        a0.w = (a0.w + a1.w) * inv;
        *reinterpret_cast<float4*>(out + (size_t)gwarp * D + c) = a0;
    }
}

// ---------------------------------------------------------------------------
// Launch
// Inputs (metadata order): d_in[0] = x (float32, E*D), d_in[1] = index (E,
// int32 or int64 — detected on device), d_in[2] = dim_size (unused).
// ---------------------------------------------------------------------------
extern "C" void kernel_launch(void* const* d_in, const int* in_sizes, int n_in,
                              void* d_out, int out_size) {
    const float*        x   = (const float*)d_in[0];
    const unsigned int* idx = (const unsigned int*)d_in[1];
    float*              out = (float*)d_out;

    int E = in_sizes[1];          // 640000
    int D = in_sizes[0] / E;      // 128
    int N = out_size / D;         // 100000

    // Kernel 1: segment boundaries via guided search (N+1 threads).
    {
        int threads = 256;
        int blocks = (N + 1 + threads - 1) / threads;
        build_offsets_kernel<<<blocks, threads>>>(idx, E, N);
    }

    // Kernel 2: one warp per segment, 8 warps per 256-thread block.
    {
        int threads = 256;
        int warps_per_block = threads / 32;
        int blocks = (N + warps_per_block - 1) / warps_per_block;
        segment_mean_kernel<<<blocks, threads>>>(x, out, D, N);
    }
}